// round 12
// baseline (speedup 1.0000x reference)
#include <cuda_runtime.h>
#include <cuda_bf16.h>
#include <cstdint>

#define SEQ 2048
#define NB 2
#define NH 16
#define AD 64
#define DM 1024
#define BH (NB*NH)
#define NPE 33
typedef __nv_bfloat16 bf16;

// ---------------- scratch (no allocation allowed) ----------------
__device__ bf16 g_Wth[(size_t)4*DM*DM], g_Wtl[(size_t)4*DM*DM];
__device__ bf16 g_Xh[(size_t)3*NB*SEQ*DM],  g_Xl[(size_t)3*NB*SEQ*DM];
__device__ bf16 g_QKVh[(size_t)3*BH*SEQ*AD], g_QKVl[(size_t)3*BH*SEQ*AD];
__device__ bf16 g_Ch[(size_t)NB*SEQ*DM],  g_Cl[(size_t)NB*SEQ*DM];

// ---------------- helpers ----------------
__device__ __forceinline__ uint32_t s2u(const void* p) {
    uint32_t a;
    asm("{ .reg .u64 t; cvta.to.shared.u64 t, %1; cvt.u32.u64 %0, t; }" : "=r"(a) : "l"(p));
    return a;
}
__device__ __forceinline__ uint32_t swz(uint32_t o) { return o ^ ((o >> 3) & 0x70); } // SW128
__device__ __forceinline__ float ex2f(float x) {
    float r; asm("ex2.approx.f32 %0, %1;" : "=f"(r) : "f"(x)); return r;
}

__device__ __forceinline__ void ldsm4(uint32_t* r, uint32_t a) {
    asm volatile("ldmatrix.sync.aligned.m8n8.x4.shared.b16 {%0,%1,%2,%3}, [%4];"
                 : "=r"(r[0]), "=r"(r[1]), "=r"(r[2]), "=r"(r[3]) : "r"(a));
}
__device__ __forceinline__ void ldsm4t(uint32_t* r, uint32_t a) {
    asm volatile("ldmatrix.sync.aligned.m8n8.x4.trans.shared.b16 {%0,%1,%2,%3}, [%4];"
                 : "=r"(r[0]), "=r"(r[1]), "=r"(r[2]), "=r"(r[3]) : "r"(a));
}
__device__ __forceinline__ void mma_bf16(float* d, const uint32_t* a, const uint32_t* b) {
    asm volatile("mma.sync.aligned.m16n8k16.row.col.f32.bf16.bf16.f32 "
                 "{%0,%1,%2,%3}, {%4,%5,%6,%7}, {%8,%9}, {%0,%1,%2,%3};"
                 : "+f"(d[0]), "+f"(d[1]), "+f"(d[2]), "+f"(d[3])
                 : "r"(a[0]), "r"(a[1]), "r"(a[2]), "r"(a[3]), "r"(b[0]), "r"(b[1]));
}
#define CP16(dst, src) \
    asm volatile("cp.async.cg.shared.global [%0], [%1], 16;" :: "r"(dst), "l"(src))
#define CPCOMMIT asm volatile("cp.async.commit_group;" ::: "memory")
#define CPWAIT(n) asm volatile("cp.async.wait_group %0;" :: "n"(n) : "memory")

__device__ __forceinline__ void packhl(float x0, float x1, uint32_t& ph, uint32_t& pl) {
    bf16 h0 = __float2bfloat16(x0), h1 = __float2bfloat16(x1);
    ph = ((uint32_t)__bfloat16_as_ushort(h1) << 16) | __bfloat16_as_ushort(h0);
    float l0 = x0 - __bfloat162float(h0), l1 = x1 - __bfloat162float(h1);
    asm("cvt.rn.bf16x2.f32 %0, %1, %2;" : "=r"(pl) : "f"(l1), "f"(l0));
}
__device__ __forceinline__ void cvt_hl(float4 v, uint2& h2, uint2& l2) {
    uint32_t a, b, c, d;
    packhl(v.x, v.y, a, c);
    packhl(v.z, v.w, b, d);
    h2 = make_uint2(a, b); l2 = make_uint2(c, d);
}

// ---------------- prep kernels ----------------
__global__ __launch_bounds__(256)
void split_in3(const float4* __restrict__ x0, const float4* __restrict__ x1,
               const float4* __restrict__ x2, bf16* __restrict__ h, bf16* __restrict__ l)
{
    const float4* x = (blockIdx.y == 0) ? x0 : (blockIdx.y == 1) ? x1 : x2;
    const size_t sec = (size_t)blockIdx.y * NB * SEQ * DM;
    size_t i = (size_t)blockIdx.x * 256 + threadIdx.x;
    float4 v = x[i];
    uint2 h2, l2; cvt_hl(v, h2, l2);
    *reinterpret_cast<uint2*>(h + sec + i * 4) = h2;
    *reinterpret_cast<uint2*>(l + sec + i * 4) = l2;
}

__global__ __launch_bounds__(256)
void transp_w(const float* __restrict__ W0, const float* __restrict__ W1,
              const float* __restrict__ W2, const float* __restrict__ W3,
              bf16* __restrict__ oh, bf16* __restrict__ ol)
{
    __shared__ float t[32][33];
    const float* W = (blockIdx.z == 0) ? W0 : (blockIdx.z == 1) ? W1
                   : (blockIdx.z == 2) ? W2 : W3;
    bf16* Oh = oh + (size_t)blockIdx.z * DM * DM;
    bf16* Ol = ol + (size_t)blockIdx.z * DM * DM;
    const int tx = threadIdx.x & 31, ty = threadIdx.x >> 5;
    const int x = blockIdx.x * 32 + tx, y = blockIdx.y * 32 + ty;
    #pragma unroll
    for (int j = 0; j < 32; j += 8) t[ty + j][tx] = W[(size_t)(y + j) * DM + x];
    __syncthreads();
    const int xo = blockIdx.y * 32 + tx, yo = blockIdx.x * 32 + ty;
    #pragma unroll
    for (int j = 0; j < 32; j += 8) {
        float v = t[tx][ty + j];
        bf16 h = __float2bfloat16(v);
        Oh[(size_t)(yo + j) * DM + xo] = h;
        Ol[(size_t)(yo + j) * DM + xo] = __float2bfloat16(v - __bfloat162float(h));
    }
}

// ---------------------------------------------------------------------------
// split-bf16 GEMM, BK=32, hi/lo interleaved 128B SW128 rows, 3-stage ring,
// one __syncthreads per k-step, 2 CTAs/SM.
// ---------------------------------------------------------------------------
template<int EPI>
__global__ __launch_bounds__(256, 2)
void gemm_hl(const bf16* __restrict__ Ah_g, const bf16* __restrict__ Al_g,
             const bf16* __restrict__ Bh_g, const bf16* __restrict__ Bl_g,
             float* __restrict__ Cf, bf16* __restrict__ Oh, bf16* __restrict__ Ol,
             int K, long sA, long sB, long sO)
{
    extern __shared__ char dsm[];
    const uint32_t sb = s2u(dsm);
    const int tid = threadIdx.x, wid = tid >> 5, lane = tid & 31;
    const int z = blockIdx.z;
    Ah_g += (size_t)z * sA;  Al_g += (size_t)z * sA;
    Bh_g += (size_t)z * sB;  Bl_g += (size_t)z * sB;
    const int bm = blockIdx.y * 128, bn = blockIdx.x * 128;
    const int wm = (wid >> 1) * 32, wn = (wid & 1) * 64;

    float acc[2][8][4] = {};

    auto load_stage = [&](int buf, int k0) {
        const uint32_t base = sb + (uint32_t)buf * 32768u;
        #pragma unroll
        for (int i = 0; i < 8; i++) {
            int c = tid + i * 256;
            int reg = c >> 10;
            int row = (c >> 3) & 127;
            int j   = c & 7;
            const bool hi = (j < 4);
            const int jj = hi ? j : j - 4;
            const bf16* src = (reg == 0)
                ? (hi ? Ah_g : Al_g) + (size_t)(bm + row) * K + k0 + jj * 8
                : (hi ? Bh_g : Bl_g) + (size_t)(bn + row) * K + k0 + jj * 8;
            const uint32_t o = (uint32_t)row * 128u + (uint32_t)j * 16u;
            CP16(base + (uint32_t)reg * 16384u + swz(o), src);
        }
        CPCOMMIT;
    };

    const int NS = K / 32;
    load_stage(0, 0);
    load_stage(1, 32);
    for (int s = 0; s < NS; s++) {
        if (s < NS - 1) { CPWAIT(1); } else { CPWAIT(0); }
        __syncthreads();
        if (s + 2 < NS) load_stage((s + 2) % 3, (s + 2) * 32);

        const uint32_t AB_ = sb + (uint32_t)(s % 3) * 32768u;
        const uint32_t BB_ = AB_ + 16384u;
        #pragma unroll
        for (int kk = 0; kk < 2; kk++) {
            const uint32_t kB = (uint32_t)kk * 32u;
            uint32_t ah[2][4], al_[2][4];
            const uint32_t aoff = (((uint32_t)lane >> 4) << 4) + kB;
            #pragma unroll
            for (int mt = 0; mt < 2; mt++) {
                const uint32_t rowb = (uint32_t)(wm + mt * 16 + (lane & 15)) * 128u;
                ldsm4(ah[mt],  AB_ + swz(rowb + aoff));
                ldsm4(al_[mt], AB_ + swz(rowb + aoff + 64u));
            }
            const uint32_t boff = ((((uint32_t)lane >> 3) & 1u) << 4) + kB;
            const uint32_t brow = (uint32_t)(wn + (lane & 7) + ((lane >> 4) << 3));
            #pragma unroll
            for (int g = 0; g < 4; g++) {
                uint32_t bh4[4], bl4[4];
                const uint32_t rowb = (brow + (uint32_t)g * 16u) * 128u;
                ldsm4(bh4, BB_ + swz(rowb + boff));
                ldsm4(bl4, BB_ + swz(rowb + boff + 64u));
                #pragma unroll
                for (int mt = 0; mt < 2; mt++)
                    #pragma unroll
                    for (int q = 0; q < 2; q++) {
                        mma_bf16(acc[mt][g * 2 + q], ah[mt],  bh4 + q * 2);
                        mma_bf16(acc[mt][g * 2 + q], ah[mt],  bl4 + q * 2);
                        mma_bf16(acc[mt][g * 2 + q], al_[mt], bh4 + q * 2);
                    }
            }
        }
    }

    #pragma unroll
    for (int mt = 0; mt < 2; mt++)
        #pragma unroll
        for (int nt = 0; nt < 8; nt++) {
            const int m = bm + wm + mt * 16 + (lane >> 2);
            const int n = bn + wn + nt * 8 + (lane & 3) * 2;
            #pragma unroll
            for (int rr = 0; rr < 2; rr++) {
                const int mm = m + rr * 8;
                const float x0 = acc[mt][nt][rr * 2 + 0], x1 = acc[mt][nt][rr * 2 + 1];
                if constexpr (EPI == 0) {
                    *reinterpret_cast<float2*>(Cf + (size_t)mm * DM + n) = make_float2(x0, x1);
                } else {
                    const int b_ = mm >> 11, s_ = mm & 2047, h_ = n >> 6, d_ = n & 63;
                    const size_t o = (size_t)z * sO +
                        (((size_t)(b_ * NH + h_)) * SEQ + s_) * AD + d_;
                    uint32_t ph, pl; packhl(x0, x1, ph, pl);
                    *reinterpret_cast<uint32_t*>(Oh + o) = ph;
                    *reinterpret_cast<uint32_t*>(Ol + o) = pl;
                }
            }
        }
}

// ---------------------------------------------------------------------------
// fused flash attention v3: BQ=128 per CTA (4 warps, 32 q-rows each, 2 m-tiles),
// BS=64 stages, 2 CTAs/SM.  Each K/V ldmatrix feeds 2 m-tiles of MMAs.
// ---------------------------------------------------------------------------
__global__ __launch_bounds__(128, 2)
void flash_attn(const bf16* __restrict__ Qh_g, const bf16* __restrict__ Ql_g,
                const bf16* __restrict__ Kh_g, const bf16* __restrict__ Kl_g,
                const bf16* __restrict__ Vh_g, const bf16* __restrict__ Vl_g,
                const float* __restrict__ pemb,
                bf16* __restrict__ Ch, bf16* __restrict__ Cl)
{
    extern __shared__ char sp[];
    const uint32_t sb = s2u(sp);
    const int tid = threadIdx.x, wid = tid >> 5, lane = tid & 31;
    const int bh = blockIdx.y, bm = blockIdx.x * 128;
    const int wm = wid * 32;
    constexpr float CEXP = 0.18033688f;   // log2(e)/8

    const bf16* Qh = Qh_g + ((size_t)bh * SEQ + bm) * AD;
    const bf16* Ql = Ql_g + ((size_t)bh * SEQ + bm) * AD;
    const bf16* Kh = Kh_g + (size_t)bh * SEQ * AD;
    const bf16* Kl = Kl_g + (size_t)bh * SEQ * AD;
    const bf16* Vh = Vh_g + (size_t)bh * SEQ * AD;
    const bf16* Vl = Vl_g + (size_t)bh * SEQ * AD;

    // smem: Qh 16K | Ql 16K | 2 stages x 32K | prow bf16 128x33 | pemb bf16 33x64
    constexpr uint32_t QOFF = 0, STG = 32768;
    constexpr uint32_t PROW = STG + 2 * 32768;            // 98304
    constexpr uint32_t PEMB = PROW + 128 * NPE * 2;       // 106752 ; total 110976
    bf16* prowB = reinterpret_cast<bf16*>(sp + PROW);
    bf16* pembS = reinterpret_cast<bf16*>(sp + PEMB);

    auto load_stage = [&](int buf, int s0) {
        uint32_t base = sb + STG + (uint32_t)buf * 32768u;
        #pragma unroll
        for (int i = 0; i < 16; i++) {
            int c = tid + i * 128;
            int t_ = c >> 9, row = (c >> 3) & 63, j = c & 7;
            const bf16* src =
                (t_ == 0) ? Kh + (size_t)(s0 + row) * AD + j * 8 :
                (t_ == 1) ? Kl + (size_t)(s0 + row) * AD + j * 8 :
                (t_ == 2) ? Vh + (size_t)(s0 + row) * AD + j * 8 :
                            Vl + (size_t)(s0 + row) * AD + j * 8;
            uint32_t dst = base + (uint32_t)t_ * 8192u +
                           swz((uint32_t)row * 128u + (uint32_t)j * 16u);
            CP16(dst, src);
        }
        CPCOMMIT;
    };

    // Q (hi/lo, 128 rows) + stage 0 committed together
    {
        #pragma unroll
        for (int i = 0; i < 16; i++) {
            int c = tid + i * 128;
            int t_ = c >> 10, row = (c >> 3) & 127, j = c & 7;
            const bf16* src = (t_ ? Ql : Qh) + (size_t)row * AD + j * 8;
            uint32_t dst = sb + QOFF + (uint32_t)t_ * 16384u +
                           swz((uint32_t)row * 128u + (uint32_t)j * 16u);
            CP16(dst, src);
        }
    }
    load_stage(0, 0);

    // ---- prologue: prow[r][j] = Q[r]·pemb[j], one thread per q-row ----
    {
        for (int i = tid; i < NPE * AD; i += 128)
            pembS[i] = __float2bfloat16(pemb[i]);
        const int r = tid;
        float qreg[64];
        {
            const bf16* qh = Qh + (size_t)r * AD;
            const bf16* ql = Ql + (size_t)r * AD;
            #pragma unroll
            for (int d2 = 0; d2 < 32; d2++) {
                __nv_bfloat162 hv = *reinterpret_cast<const __nv_bfloat162*>(qh + d2 * 2);
                __nv_bfloat162 lv = *reinterpret_cast<const __nv_bfloat162*>(ql + d2 * 2);
                float2 hf = __bfloat1622float2(hv), lf = __bfloat1622float2(lv);
                qreg[d2 * 2 + 0] = hf.x + lf.x;
                qreg[d2 * 2 + 1] = hf.y + lf.y;
            }
        }
        __syncthreads();   // pembS ready
        #pragma unroll 1
        for (int j = 0; j < NPE; j++) {
            float a = 0.f;
            #pragma unroll
            for (int d2 = 0; d2 < 32; d2++) {
                float2 pe = __bfloat1622float2(
                    *reinterpret_cast<const __nv_bfloat162*>(pembS + j * AD + d2 * 2));
                a += qreg[d2 * 2] * pe.x + qreg[d2 * 2 + 1] * pe.y;
            }
            prowB[r * NPE + j] = __float2bfloat16(a);
        }
        __syncthreads();
    }

    float ctx[2][8][4] = {};
    float mrun[2][2] = {{-1e30f, -1e30f}, {-1e30f, -1e30f}};
    float lrun[2][2] = {};
    float blo[2][2], bhi[2][2];
    #pragma unroll
    for (int mt = 0; mt < 2; mt++)
        #pragma unroll
        for (int rr = 0; rr < 2; rr++) {
            const int l = wm + mt * 16 + (lane >> 2) + rr * 8;
            blo[mt][rr] = __bfloat162float(prowB[l * NPE + 0]);
            bhi[mt][rr] = __bfloat162float(prowB[l * NPE + 32]);
        }

    for (int st = 0; st < 32; st++) {
        if (st + 1 < 32) { load_stage((st + 1) & 1, (st + 1) * 64); CPWAIT(1); }
        else             { CPWAIT(0); }
        __syncthreads();

        const uint32_t base = sb + STG + (uint32_t)(st & 1) * 32768u;
        const uint32_t KhB = base, KlB = base + 8192u, VhB = base + 16384u, VlB = base + 24576u;

        // ---- S = Q K^T (unscaled), q-frags reloaded per kk ----
        float tS[2][8][4];
        #pragma unroll
        for (int mt = 0; mt < 2; mt++)
            #pragma unroll
            for (int nt = 0; nt < 8; nt++)
                #pragma unroll
                for (int e = 0; e < 4; e++) tS[mt][nt][e] = 0.f;

        #pragma unroll
        for (int kk = 0; kk < 4; kk++) {
            uint32_t qah[2][4], qal[2][4];
            const uint32_t aoff = (((uint32_t)lane >> 4) << 4) + (uint32_t)kk * 32u;
            #pragma unroll
            for (int mt = 0; mt < 2; mt++) {
                const uint32_t sw = swz((uint32_t)(wm + mt * 16 + (lane & 15)) * 128u + aoff);
                ldsm4(qah[mt], sb + QOFF + sw);
                ldsm4(qal[mt], sb + QOFF + 16384u + sw);
            }
            const uint32_t boff = ((((uint32_t)lane >> 3) & 1u) << 4) + (uint32_t)kk * 32u;
            const uint32_t brow = (uint32_t)((lane & 7) + ((lane >> 4) << 3));
            #pragma unroll
            for (int g = 0; g < 4; g++) {
                uint32_t bh4[4], bl4[4];
                const uint32_t sw = swz((brow + (uint32_t)g * 16u) * 128u + boff);
                ldsm4(bh4, KhB + sw);
                ldsm4(bl4, KlB + sw);
                #pragma unroll
                for (int mt = 0; mt < 2; mt++)
                    #pragma unroll
                    for (int q = 0; q < 2; q++) {
                        mma_bf16(tS[mt][g * 2 + q], qah[mt], bh4 + q * 2);
                        mma_bf16(tS[mt][g * 2 + q], qah[mt], bl4 + q * 2);
                        mma_bf16(tS[mt][g * 2 + q], qal[mt], bh4 + q * 2);
                    }
            }
        }

        // ---- bias (unscaled) ----
        const int sbase = st * 64, qmin = bm + wm;
        if (sbase + 63 <= qmin - 16) {
            #pragma unroll
            for (int mt = 0; mt < 2; mt++)
                #pragma unroll
                for (int nt = 0; nt < 8; nt++)
                    #pragma unroll
                    for (int e = 0; e < 4; e++)
                        tS[mt][nt][e] += blo[mt][e >> 1];
        } else if (sbase >= qmin + 47) {
            #pragma unroll
            for (int mt = 0; mt < 2; mt++)
                #pragma unroll
                for (int nt = 0; nt < 8; nt++)
                    #pragma unroll
                    for (int e = 0; e < 4; e++)
                        tS[mt][nt][e] += bhi[mt][e >> 1];
        } else {
            #pragma unroll
            for (int mt = 0; mt < 2; mt++)
                #pragma unroll
                for (int nt = 0; nt < 8; nt++)
                    #pragma unroll
                    for (int e = 0; e < 4; e++) {
                        const int sg = sbase + nt * 8 + (lane & 3) * 2 + (e & 1);
                        const int l  = wm + mt * 16 + (lane >> 2) + (e >> 1) * 8;
                        int idx = sg - (bm + l) + 16;
                        idx = idx < 0 ? 0 : (idx > 32 ? 32 : idx);
                        tS[mt][nt][e] += __bfloat162float(prowB[l * NPE + idx]);
                    }
        }

        // ---- online softmax (exp2-folded) ----
        #pragma unroll
        for (int mt = 0; mt < 2; mt++) {
            float mx0 = -1e30f, mx1 = -1e30f;
            #pragma unroll
            for (int nt = 0; nt < 8; nt++) {
                mx0 = fmaxf(mx0, fmaxf(tS[mt][nt][0], tS[mt][nt][1]));
                mx1 = fmaxf(mx1, fmaxf(tS[mt][nt][2], tS[mt][nt][3]));
            }
            mx0 = fmaxf(mx0, __shfl_xor_sync(0xffffffffu, mx0, 1));
            mx0 = fmaxf(mx0, __shfl_xor_sync(0xffffffffu, mx0, 2));
            mx1 = fmaxf(mx1, __shfl_xor_sync(0xffffffffu, mx1, 1));
            mx1 = fmaxf(mx1, __shfl_xor_sync(0xffffffffu, mx1, 2));
            const float M0 = fmaxf(mrun[mt][0], mx0), M1 = fmaxf(mrun[mt][1], mx1);
            const float nmc0 = -M0 * CEXP, nmc1 = -M1 * CEXP;
            const float a0 = ex2f(fmaf(mrun[mt][0], CEXP, nmc0));
            const float a1 = ex2f(fmaf(mrun[mt][1], CEXP, nmc1));
            mrun[mt][0] = M0; mrun[mt][1] = M1;
            float s0 = 0.f, s1 = 0.f;
            #pragma unroll
            for (int nt = 0; nt < 8; nt++) {
                tS[mt][nt][0] = ex2f(fmaf(tS[mt][nt][0], CEXP, nmc0)); s0 += tS[mt][nt][0];
                tS[mt][nt][1] = ex2f(fmaf(tS[mt][nt][1], CEXP, nmc0)); s0 += tS[mt][nt][1];
                tS[mt][nt][2] = ex2f(fmaf(tS[mt][nt][2], CEXP, nmc1)); s1 += tS[mt][nt][2];
                tS[mt][nt][3] = ex2f(fmaf(tS[mt][nt][3], CEXP, nmc1)); s1 += tS[mt][nt][3];
            }
            s0 += __shfl_xor_sync(0xffffffffu, s0, 1);
            s0 += __shfl_xor_sync(0xffffffffu, s0, 2);
            s1 += __shfl_xor_sync(0xffffffffu, s1, 1);
            s1 += __shfl_xor_sync(0xffffffffu, s1, 2);
            lrun[mt][0] = lrun[mt][0] * a0 + s0;
            lrun[mt][1] = lrun[mt][1] * a1 + s1;
            #pragma unroll
            for (int g = 0; g < 8; g++) {
                ctx[mt][g][0] *= a0; ctx[mt][g][1] *= a0;
                ctx[mt][g][2] *= a1; ctx[mt][g][3] *= a1;
            }
        }

        // ---- ctx += P V (V frags shared across 2 m-tiles) ----
        #pragma unroll
        for (int c = 0; c < 4; c++) {
            uint32_t ph4[2][4], pl4[2][4];
            #pragma unroll
            for (int mt = 0; mt < 2; mt++) {
                packhl(tS[mt][2*c][0],   tS[mt][2*c][1],   ph4[mt][0], pl4[mt][0]);
                packhl(tS[mt][2*c][2],   tS[mt][2*c][3],   ph4[mt][1], pl4[mt][1]);
                packhl(tS[mt][2*c+1][0], tS[mt][2*c+1][1], ph4[mt][2], pl4[mt][2]);
                packhl(tS[mt][2*c+1][2], tS[mt][2*c+1][3], ph4[mt][3], pl4[mt][3]);
            }
            const uint32_t vrow  = (uint32_t)(c * 16 + (lane & 7) + ((lane >> 3) & 1) * 8);
            const uint32_t vcolb = (((uint32_t)lane >> 4) << 4);
            #pragma unroll
            for (int g = 0; g < 4; g++) {
                uint32_t vh4[4], vl4[4];
                const uint32_t sw = swz(vrow * 128u + vcolb + (uint32_t)g * 32u);
                ldsm4t(vh4, VhB + sw);
                ldsm4t(vl4, VlB + sw);
                #pragma unroll
                for (int mt = 0; mt < 2; mt++)
                    #pragma unroll
                    for (int q = 0; q < 2; q++) {
                        mma_bf16(ctx[mt][g * 2 + q], ph4[mt], vh4 + q * 2);
                        mma_bf16(ctx[mt][g * 2 + q], ph4[mt], vl4 + q * 2);
                        mma_bf16(ctx[mt][g * 2 + q], pl4[mt], vh4 + q * 2);
                    }
            }
        }
        __syncthreads();
    }

    // ---- epilogue ----
    const int b_ = bh >> 4, h_ = bh & 15;
    #pragma unroll
    for (int mt = 0; mt < 2; mt++) {
        const float inv0 = 1.f / lrun[mt][0], inv1 = 1.f / lrun[mt][1];
        const int q0 = bm + wm + mt * 16 + (lane >> 2);
        #pragma unroll
        for (int g = 0; g < 8; g++) {
            const int col = h_ * 64 + g * 8 + (lane & 3) * 2;
            #pragma unroll
            for (int rr = 0; rr < 2; rr++) {
                const int q = q0 + rr * 8;
                const float inv = rr ? inv1 : inv0;
                const float x0 = ctx[mt][g][rr * 2 + 0] * inv, x1 = ctx[mt][g][rr * 2 + 1] * inv;
                uint32_t ph, pl; packhl(x0, x1, ph, pl);
                const size_t o = ((size_t)b_ * SEQ + q) * DM + col;
                *reinterpret_cast<uint32_t*>(Ch + o) = ph;
                *reinterpret_cast<uint32_t*>(Cl + o) = pl;
            }
        }
    }
}

// ---------------- launch ----------------
extern "C" void kernel_launch(void* const* d_in, const int* in_sizes, int n_in,
                              void* d_out, int out_size)
{
    const float* iQ   = (const float*)d_in[0];
    const float* iK   = (const float*)d_in[1];
    const float* iV   = (const float*)d_in[2];
    const float* Wq   = (const float*)d_in[3];
    const float* Wk   = (const float*)d_in[4];
    const float* Wv   = (const float*)d_in[5];
    const float* Wo   = (const float*)d_in[6];
    const float* pemb = (const float*)d_in[7];
    float* out = (float*)d_out;

    bf16 *Wth, *Wtl, *Xh, *Xl, *QKVh, *QKVl, *Ch, *Cl;
    cudaGetSymbolAddress((void**)&Wth,  g_Wth);
    cudaGetSymbolAddress((void**)&Wtl,  g_Wtl);
    cudaGetSymbolAddress((void**)&Xh,   g_Xh);
    cudaGetSymbolAddress((void**)&Xl,   g_Xl);
    cudaGetSymbolAddress((void**)&QKVh, g_QKVh);
    cudaGetSymbolAddress((void**)&QKVl, g_QKVl);
    cudaGetSymbolAddress((void**)&Ch,   g_Ch);
    cudaGetSymbolAddress((void**)&Cl,   g_Cl);

    constexpr size_t SEC = (size_t)BH * SEQ * AD;
    constexpr long   SXA = (long)NB * SEQ * DM;

    constexpr int SM_GEMM  = 3 * 32768;                          // 98304
    constexpr int SM_FLASH = 32768 + 2 * 32768
                           + 128 * NPE * 2 + NPE * AD * 2;       // 110976
    cudaFuncSetAttribute(gemm_hl<0>, cudaFuncAttributeMaxDynamicSharedMemorySize, SM_GEMM);
    cudaFuncSetAttribute(gemm_hl<1>, cudaFuncAttributeMaxDynamicSharedMemorySize, SM_GEMM);
    cudaFuncSetAttribute(flash_attn, cudaFuncAttributeMaxDynamicSharedMemorySize, SM_FLASH);

    // 0) prep
    transp_w<<<dim3(DM / 32, DM / 32, 4), 256>>>(Wq, Wk, Wv, Wo, Wth, Wtl);
    split_in3<<<dim3(NB * SEQ * DM / 4 / 256, 3), 256>>>(
        (const float4*)iQ, (const float4*)iK, (const float4*)iV, Xh, Xl);

    // 1) projections (batched z = {Q,K,V})
    gemm_hl<1><<<dim3(8, 32, 3), 256, SM_GEMM>>>(
        Xh, Xl, Wth, Wtl, nullptr, QKVh, QKVl, DM, SXA, (long)DM * DM, (long)SEC);

    // 2) fused attention
    flash_attn<<<dim3(SEQ / 128, BH), 128, SM_FLASH>>>(
        QKVh, QKVl, QKVh + SEC, QKVl + SEC, QKVh + 2 * SEC, QKVl + 2 * SEC, pemb, Ch, Cl);

    // 3) out = ctx @ Wo
    gemm_hl<0><<<dim3(8, 32, 1), 256, SM_GEMM>>>(
        Ch, Cl, Wth + (size_t)3 * DM * DM, Wtl + (size_t)3 * DM * DM,
        out, nullptr, nullptr, DM, 0, 0, 0);
}

// round 13
// speedup vs baseline: 1.0455x; 1.0455x over previous
#include <cuda_runtime.h>
#include <cuda_bf16.h>
#include <cstdint>

#define SEQ 2048
#define NB 2
#define NH 16
#define AD 64
#define DM 1024
#define BH (NB*NH)
#define NPE 33
typedef __nv_bfloat16 bf16;

// ---------------- scratch (no allocation allowed) ----------------
__device__ bf16 g_Wth[(size_t)4*DM*DM], g_Wtl[(size_t)4*DM*DM];
__device__ bf16 g_Xh[(size_t)3*NB*SEQ*DM],  g_Xl[(size_t)3*NB*SEQ*DM];
__device__ bf16 g_QKVh[(size_t)3*BH*SEQ*AD], g_QKVl[(size_t)3*BH*SEQ*AD];
__device__ bf16 g_Ch[(size_t)NB*SEQ*DM],  g_Cl[(size_t)NB*SEQ*DM];

// ---------------- helpers ----------------
__device__ __forceinline__ uint32_t s2u(const void* p) {
    uint32_t a;
    asm("{ .reg .u64 t; cvta.to.shared.u64 t, %1; cvt.u32.u64 %0, t; }" : "=r"(a) : "l"(p));
    return a;
}
__device__ __forceinline__ uint32_t swz(uint32_t o) { return o ^ ((o >> 3) & 0x70); } // SW128
__device__ __forceinline__ float ex2f(float x) {
    float r; asm("ex2.approx.f32 %0, %1;" : "=f"(r) : "f"(x)); return r;
}

__device__ __forceinline__ void ldsm4(uint32_t* r, uint32_t a) {
    asm volatile("ldmatrix.sync.aligned.m8n8.x4.shared.b16 {%0,%1,%2,%3}, [%4];"
                 : "=r"(r[0]), "=r"(r[1]), "=r"(r[2]), "=r"(r[3]) : "r"(a));
}
__device__ __forceinline__ void ldsm4t(uint32_t* r, uint32_t a) {
    asm volatile("ldmatrix.sync.aligned.m8n8.x4.trans.shared.b16 {%0,%1,%2,%3}, [%4];"
                 : "=r"(r[0]), "=r"(r[1]), "=r"(r[2]), "=r"(r[3]) : "r"(a));
}
__device__ __forceinline__ void mma_bf16(float* d, const uint32_t* a, const uint32_t* b) {
    asm volatile("mma.sync.aligned.m16n8k16.row.col.f32.bf16.bf16.f32 "
                 "{%0,%1,%2,%3}, {%4,%5,%6,%7}, {%8,%9}, {%0,%1,%2,%3};"
                 : "+f"(d[0]), "+f"(d[1]), "+f"(d[2]), "+f"(d[3])
                 : "r"(a[0]), "r"(a[1]), "r"(a[2]), "r"(a[3]), "r"(b[0]), "r"(b[1]));
}
#define CP16(dst, src) \
    asm volatile("cp.async.cg.shared.global [%0], [%1], 16;" :: "r"(dst), "l"(src))
#define CPCOMMIT asm volatile("cp.async.commit_group;" ::: "memory")
#define CPWAIT(n) asm volatile("cp.async.wait_group %0;" :: "n"(n) : "memory")

__device__ __forceinline__ void packhl(float x0, float x1, uint32_t& ph, uint32_t& pl) {
    bf16 h0 = __float2bfloat16(x0), h1 = __float2bfloat16(x1);
    ph = ((uint32_t)__bfloat16_as_ushort(h1) << 16) | __bfloat16_as_ushort(h0);
    float l0 = x0 - __bfloat162float(h0), l1 = x1 - __bfloat162float(h1);
    asm("cvt.rn.bf16x2.f32 %0, %1, %2;" : "=r"(pl) : "f"(l1), "f"(l0));
}
__device__ __forceinline__ void cvt_hl(float4 v, uint2& h2, uint2& l2) {
    uint32_t a, b, c, d;
    packhl(v.x, v.y, a, c);
    packhl(v.z, v.w, b, d);
    h2 = make_uint2(a, b); l2 = make_uint2(c, d);
}

// ---------------- prep kernels ----------------
__global__ __launch_bounds__(256)
void split_in3(const float4* __restrict__ x0, const float4* __restrict__ x1,
               const float4* __restrict__ x2, bf16* __restrict__ h, bf16* __restrict__ l)
{
    const float4* x = (blockIdx.y == 0) ? x0 : (blockIdx.y == 1) ? x1 : x2;
    const size_t sec = (size_t)blockIdx.y * NB * SEQ * DM;
    size_t i = (size_t)blockIdx.x * 256 + threadIdx.x;
    float4 v = x[i];
    uint2 h2, l2; cvt_hl(v, h2, l2);
    *reinterpret_cast<uint2*>(h + sec + i * 4) = h2;
    *reinterpret_cast<uint2*>(l + sec + i * 4) = l2;
}

__global__ __launch_bounds__(256)
void transp_w(const float* __restrict__ W0, const float* __restrict__ W1,
              const float* __restrict__ W2, const float* __restrict__ W3,
              bf16* __restrict__ oh, bf16* __restrict__ ol)
{
    __shared__ float t[32][33];
    const float* W = (blockIdx.z == 0) ? W0 : (blockIdx.z == 1) ? W1
                   : (blockIdx.z == 2) ? W2 : W3;
    bf16* Oh = oh + (size_t)blockIdx.z * DM * DM;
    bf16* Ol = ol + (size_t)blockIdx.z * DM * DM;
    const int tx = threadIdx.x & 31, ty = threadIdx.x >> 5;
    const int x = blockIdx.x * 32 + tx, y = blockIdx.y * 32 + ty;
    #pragma unroll
    for (int j = 0; j < 32; j += 8) t[ty + j][tx] = W[(size_t)(y + j) * DM + x];
    __syncthreads();
    const int xo = blockIdx.y * 32 + tx, yo = blockIdx.x * 32 + ty;
    #pragma unroll
    for (int j = 0; j < 32; j += 8) {
        float v = t[tx][ty + j];
        bf16 h = __float2bfloat16(v);
        Oh[(size_t)(yo + j) * DM + xo] = h;
        Ol[(size_t)(yo + j) * DM + xo] = __float2bfloat16(v - __bfloat162float(h));
    }
}

// ---------------------------------------------------------------------------
// split-bf16 GEMM, BK=32, hi/lo interleaved 128B SW128 rows, 2 CTAs/SM.
// MMAs ordered term-major: same-accumulator distance = 4.
// ---------------------------------------------------------------------------
template<int EPI>
__global__ __launch_bounds__(256, 2)
void gemm_hl(const bf16* __restrict__ Ah_g, const bf16* __restrict__ Al_g,
             const bf16* __restrict__ Bh_g, const bf16* __restrict__ Bl_g,
             float* __restrict__ Cf, bf16* __restrict__ Oh, bf16* __restrict__ Ol,
             int K, long sA, long sB, long sO)
{
    extern __shared__ char dsm[];
    const uint32_t sb = s2u(dsm);
    const int tid = threadIdx.x, wid = tid >> 5, lane = tid & 31;
    const int z = blockIdx.z;
    Ah_g += (size_t)z * sA;  Al_g += (size_t)z * sA;
    Bh_g += (size_t)z * sB;  Bl_g += (size_t)z * sB;
    const int bm = blockIdx.y * 128, bn = blockIdx.x * 128;
    const int wm = (wid >> 1) * 32, wn = (wid & 1) * 64;

    float acc[2][8][4] = {};

    auto load_stage = [&](int buf, int k0) {
        const uint32_t base = sb + (uint32_t)buf * 32768u;
        #pragma unroll
        for (int i = 0; i < 8; i++) {
            int c = tid + i * 256;
            int reg = c >> 10;
            int row = (c >> 3) & 127;
            int j   = c & 7;
            const bool hi = (j < 4);
            const int jj = hi ? j : j - 4;
            const bf16* src = (reg == 0)
                ? (hi ? Ah_g : Al_g) + (size_t)(bm + row) * K + k0 + jj * 8
                : (hi ? Bh_g : Bl_g) + (size_t)(bn + row) * K + k0 + jj * 8;
            const uint32_t o = (uint32_t)row * 128u + (uint32_t)j * 16u;
            CP16(base + (uint32_t)reg * 16384u + swz(o), src);
        }
        CPCOMMIT;
    };

    const int NS = K / 32;
    load_stage(0, 0);
    for (int s = 0; s < NS; s++) {
        if (s + 1 < NS) { load_stage((s + 1) & 1, (s + 1) * 32); CPWAIT(1); }
        else            { CPWAIT(0); }
        __syncthreads();
        const uint32_t AB_ = sb + (uint32_t)(s & 1) * 32768u;
        const uint32_t BB_ = AB_ + 16384u;
        #pragma unroll
        for (int kk = 0; kk < 2; kk++) {
            const uint32_t kB = (uint32_t)kk * 32u;
            uint32_t ah[2][4], al_[2][4];
            const uint32_t aoff = (((uint32_t)lane >> 4) << 4) + kB;
            #pragma unroll
            for (int mt = 0; mt < 2; mt++) {
                const uint32_t rowb = (uint32_t)(wm + mt * 16 + (lane & 15)) * 128u;
                ldsm4(ah[mt],  AB_ + swz(rowb + aoff));
                ldsm4(al_[mt], AB_ + swz(rowb + aoff + 64u));
            }
            const uint32_t boff = ((((uint32_t)lane >> 3) & 1u) << 4) + kB;
            const uint32_t brow = (uint32_t)(wn + (lane & 7) + ((lane >> 4) << 3));
            #pragma unroll
            for (int g = 0; g < 4; g++) {
                uint32_t bh4[4], bl4[4];
                const uint32_t rowb = (brow + (uint32_t)g * 16u) * 128u;
                ldsm4(bh4, BB_ + swz(rowb + boff));
                ldsm4(bl4, BB_ + swz(rowb + boff + 64u));
                // term-major: same-acc distance = 4 MMAs
                #pragma unroll
                for (int mt = 0; mt < 2; mt++)
                    #pragma unroll
                    for (int q = 0; q < 2; q++)
                        mma_bf16(acc[mt][g * 2 + q], ah[mt],  bh4 + q * 2);
                #pragma unroll
                for (int mt = 0; mt < 2; mt++)
                    #pragma unroll
                    for (int q = 0; q < 2; q++)
                        mma_bf16(acc[mt][g * 2 + q], ah[mt],  bl4 + q * 2);
                #pragma unroll
                for (int mt = 0; mt < 2; mt++)
                    #pragma unroll
                    for (int q = 0; q < 2; q++)
                        mma_bf16(acc[mt][g * 2 + q], al_[mt], bh4 + q * 2);
            }
        }
        __syncthreads();
    }

    #pragma unroll
    for (int mt = 0; mt < 2; mt++)
        #pragma unroll
        for (int nt = 0; nt < 8; nt++) {
            const int m = bm + wm + mt * 16 + (lane >> 2);
            const int n = bn + wn + nt * 8 + (lane & 3) * 2;
            #pragma unroll
            for (int rr = 0; rr < 2; rr++) {
                const int mm = m + rr * 8;
                const float x0 = acc[mt][nt][rr * 2 + 0], x1 = acc[mt][nt][rr * 2 + 1];
                if constexpr (EPI == 0) {
                    *reinterpret_cast<float2*>(Cf + (size_t)mm * DM + n) = make_float2(x0, x1);
                } else {
                    const int b_ = mm >> 11, s_ = mm & 2047, h_ = n >> 6, d_ = n & 63;
                    const size_t o = (size_t)z * sO +
                        (((size_t)(b_ * NH + h_)) * SEQ + s_) * AD + d_;
                    uint32_t ph, pl; packhl(x0, x1, ph, pl);
                    *reinterpret_cast<uint32_t*>(Oh + o) = ph;
                    *reinterpret_cast<uint32_t*>(Ol + o) = pl;
                }
            }
        }
}

// ---------------------------------------------------------------------------
// fused flash attention (R11 structure): BQ=64, 128 thr, BS=64, 2 CTAs/SM.
// MMAs re-ordered term-major with 2-g batching: same-acc distance = 4.
// ---------------------------------------------------------------------------
__global__ __launch_bounds__(128, 2)
void flash_attn(const bf16* __restrict__ Qh_g, const bf16* __restrict__ Ql_g,
                const bf16* __restrict__ Kh_g, const bf16* __restrict__ Kl_g,
                const bf16* __restrict__ Vh_g, const bf16* __restrict__ Vl_g,
                const float* __restrict__ pemb,
                bf16* __restrict__ Ch, bf16* __restrict__ Cl)
{
    extern __shared__ char dsm[];
    const uint32_t raw = s2u(dsm);
    const uint32_t sb  = (raw + 1023u) & ~1023u;
    char* sp = dsm + (sb - raw);
    const int tid = threadIdx.x, wid = tid >> 5, lane = tid & 31;
    const int bh = blockIdx.y, bm = blockIdx.x * 64;
    const int wm = wid * 16;
    constexpr float CEXP = 0.18033688f;   // log2(e)/8

    const bf16* Qh = Qh_g + ((size_t)bh * SEQ + bm) * AD;
    const bf16* Ql = Ql_g + ((size_t)bh * SEQ + bm) * AD;
    const bf16* Kh = Kh_g + (size_t)bh * SEQ * AD;
    const bf16* Kl = Kl_g + (size_t)bh * SEQ * AD;
    const bf16* Vh = Vh_g + (size_t)bh * SEQ * AD;
    const bf16* Vl = Vl_g + (size_t)bh * SEQ * AD;

    constexpr uint32_t QOFF = 0, STG = 16384;
    constexpr uint32_t PROW = STG + 2 * 32768;
    constexpr uint32_t PEMB = PROW + 64 * NPE * 4;
    float* prow  = reinterpret_cast<float*>(sp + PROW);
    float* pembS = reinterpret_cast<float*>(sp + PEMB);

    auto load_stage = [&](int buf, int s0) {
        uint32_t base = sb + STG + (uint32_t)buf * 32768u;
        #pragma unroll
        for (int i = 0; i < 16; i++) {
            int c = tid + i * 128;
            int t_ = c >> 9, row = (c >> 3) & 63, j = c & 7;
            const bf16* src =
                (t_ == 0) ? Kh + (size_t)(s0 + row) * AD + j * 8 :
                (t_ == 1) ? Kl + (size_t)(s0 + row) * AD + j * 8 :
                (t_ == 2) ? Vh + (size_t)(s0 + row) * AD + j * 8 :
                            Vl + (size_t)(s0 + row) * AD + j * 8;
            uint32_t dst = base + (uint32_t)t_ * 8192u +
                           swz((uint32_t)row * 128u + (uint32_t)j * 16u);
            CP16(dst, src);
        }
        CPCOMMIT;
    };

    // Q (hi/lo, 64 rows) + stage 0, committed together
    {
        #pragma unroll
        for (int i = 0; i < 8; i++) {
            int c = tid + i * 128;
            int t_ = c >> 9, row = (c >> 3) & 63, j = c & 7;
            const bf16* src = (t_ ? Ql : Qh) + (size_t)row * AD + j * 8;
            uint32_t dst = sb + QOFF + (uint32_t)t_ * 8192u +
                           swz((uint32_t)row * 128u + (uint32_t)j * 16u);
            CP16(dst, src);
        }
    }
    load_stage(0, 0);

    // ---- prologue: prow[r][j] = Q[r]·pemb[j] (fp32) ----
    {
        for (int i = tid; i < NPE * AD; i += 128) pembS[i] = pemb[i];
        const int r = tid & 63, half = tid >> 6;
        float qreg[32];
        {
            const bf16* qh = Qh + (size_t)r * AD + half * 32;
            const bf16* ql = Ql + (size_t)r * AD + half * 32;
            #pragma unroll
            for (int d4 = 0; d4 < 8; d4++) {
                uint2 hv = *reinterpret_cast<const uint2*>(qh + d4 * 4);
                uint2 lv = *reinterpret_cast<const uint2*>(ql + d4 * 4);
                const uint32_t hw[2] = {hv.x, hv.y}, lw[2] = {lv.x, lv.y};
                #pragma unroll
                for (int w = 0; w < 2; w++) {
                    float2 hf = __bfloat1622float2(*reinterpret_cast<const __nv_bfloat162*>(&hw[w]));
                    float2 lf = __bfloat1622float2(*reinterpret_cast<const __nv_bfloat162*>(&lw[w]));
                    qreg[d4 * 4 + w * 2 + 0] = hf.x + lf.x;
                    qreg[d4 * 4 + w * 2 + 1] = hf.y + lf.y;
                }
            }
        }
        __syncthreads();   // pembS ready
        if (half == 0) {
            #pragma unroll 1
            for (int j = 0; j < NPE; j++) {
                float a = 0.f;
                #pragma unroll
                for (int d = 0; d < 32; d++) a += qreg[d] * pembS[j * AD + d];
                prow[r * NPE + j] = a;
            }
        }
        __syncthreads();
        if (half == 1) {
            #pragma unroll 1
            for (int j = 0; j < NPE; j++) {
                float a = 0.f;
                #pragma unroll
                for (int d = 0; d < 32; d++) a += qreg[d] * pembS[j * AD + 32 + d];
                prow[r * NPE + j] += a;
            }
        }
        __syncthreads();
    }

    float ctx[8][4] = {};
    float mrun0 = -1e30f, mrun1 = -1e30f, lrun0 = 0.f, lrun1 = 0.f;
    uint32_t qah[4][4], qal[4][4];
    float blo0 = 0.f, blo1 = 0.f, bhi0 = 0.f, bhi1 = 0.f;
    const int rl0 = wm + (lane >> 2), rl1 = rl0 + 8;

    for (int st = 0; st < 32; st++) {
        if (st + 1 < 32) { load_stage((st + 1) & 1, (st + 1) * 64); CPWAIT(1); }
        else             { CPWAIT(0); }
        __syncthreads();

        if (st == 0) {
            #pragma unroll
            for (int kk = 0; kk < 4; kk++) {
                const uint32_t aoff = (((uint32_t)lane >> 4) << 4) + (uint32_t)kk * 32u;
                const uint32_t sw = swz((uint32_t)(wm + (lane & 15)) * 128u + aoff);
                ldsm4(qah[kk], sb + QOFF + sw);
                ldsm4(qal[kk], sb + QOFF + 8192u + sw);
            }
            blo0 = prow[rl0 * NPE + 0];  bhi0 = prow[rl0 * NPE + 32];
            blo1 = prow[rl1 * NPE + 0];  bhi1 = prow[rl1 * NPE + 32];
        }

        const uint32_t base = sb + STG + (uint32_t)(st & 1) * 32768u;
        const uint32_t KhB = base, KlB = base + 8192u, VhB = base + 16384u, VlB = base + 24576u;

        // ---- S = Q K^T (unscaled), term-major with 2-g batching ----
        float tS[8][4];
        #pragma unroll
        for (int nt = 0; nt < 8; nt++)
            #pragma unroll
            for (int e = 0; e < 4; e++) tS[nt][e] = 0.f;

        #pragma unroll
        for (int kk = 0; kk < 4; kk++) {
            const uint32_t boff = ((((uint32_t)lane >> 3) & 1u) << 4) + (uint32_t)kk * 32u;
            const uint32_t brow = (uint32_t)((lane & 7) + ((lane >> 4) << 3));
            #pragma unroll
            for (int gp = 0; gp < 2; gp++) {
                uint32_t bh4[2][4], bl4[2][4];
                #pragma unroll
                for (int gg = 0; gg < 2; gg++) {
                    const uint32_t sw = swz((brow + (uint32_t)(gp * 2 + gg) * 16u) * 128u + boff);
                    ldsm4(bh4[gg], KhB + sw);
                    ldsm4(bl4[gg], KlB + sw);
                }
                #pragma unroll
                for (int gg = 0; gg < 2; gg++)
                    #pragma unroll
                    for (int q = 0; q < 2; q++)
                        mma_bf16(tS[(gp * 2 + gg) * 2 + q], qah[kk], bh4[gg] + q * 2);
                #pragma unroll
                for (int gg = 0; gg < 2; gg++)
                    #pragma unroll
                    for (int q = 0; q < 2; q++)
                        mma_bf16(tS[(gp * 2 + gg) * 2 + q], qah[kk], bl4[gg] + q * 2);
                #pragma unroll
                for (int gg = 0; gg < 2; gg++)
                    #pragma unroll
                    for (int q = 0; q < 2; q++)
                        mma_bf16(tS[(gp * 2 + gg) * 2 + q], qal[kk], bh4[gg] + q * 2);
            }
        }

        // ---- bias (unscaled) ----
        const int sbase = st * 64, qmin = bm + wm;
        if (sbase + 63 <= qmin - 16) {
            #pragma unroll
            for (int nt = 0; nt < 8; nt++)
                #pragma unroll
                for (int e = 0; e < 4; e++)
                    tS[nt][e] += (e < 2) ? blo0 : blo1;
        } else if (sbase >= qmin + 31) {
            #pragma unroll
            for (int nt = 0; nt < 8; nt++)
                #pragma unroll
                for (int e = 0; e < 4; e++)
                    tS[nt][e] += (e < 2) ? bhi0 : bhi1;
        } else {
            #pragma unroll
            for (int nt = 0; nt < 8; nt++)
                #pragma unroll
                for (int e = 0; e < 4; e++) {
                    const int sg = sbase + nt * 8 + (lane & 3) * 2 + (e & 1);
                    const int rl = (e < 2) ? rl0 : rl1;
                    int idx = sg - (bm + rl) + 16;
                    idx = idx < 0 ? 0 : (idx > 32 ? 32 : idx);
                    tS[nt][e] += prow[rl * NPE + idx];
                }
        }

        // ---- online softmax (exp2-folded) ----
        float mx0 = -1e30f, mx1 = -1e30f;
        #pragma unroll
        for (int nt = 0; nt < 8; nt++) {
            mx0 = fmaxf(mx0, fmaxf(tS[nt][0], tS[nt][1]));
            mx1 = fmaxf(mx1, fmaxf(tS[nt][2], tS[nt][3]));
        }
        mx0 = fmaxf(mx0, __shfl_xor_sync(0xffffffffu, mx0, 1));
        mx0 = fmaxf(mx0, __shfl_xor_sync(0xffffffffu, mx0, 2));
        mx1 = fmaxf(mx1, __shfl_xor_sync(0xffffffffu, mx1, 1));
        mx1 = fmaxf(mx1, __shfl_xor_sync(0xffffffffu, mx1, 2));
        const float M0 = fmaxf(mrun0, mx0), M1 = fmaxf(mrun1, mx1);
        const float nmc0 = -M0 * CEXP, nmc1 = -M1 * CEXP;
        const float a0 = ex2f(fmaf(mrun0, CEXP, nmc0));
        const float a1 = ex2f(fmaf(mrun1, CEXP, nmc1));
        mrun0 = M0; mrun1 = M1;
        float s0 = 0.f, s1 = 0.f;
        #pragma unroll
        for (int nt = 0; nt < 8; nt++) {
            tS[nt][0] = ex2f(fmaf(tS[nt][0], CEXP, nmc0)); s0 += tS[nt][0];
            tS[nt][1] = ex2f(fmaf(tS[nt][1], CEXP, nmc0)); s0 += tS[nt][1];
            tS[nt][2] = ex2f(fmaf(tS[nt][2], CEXP, nmc1)); s1 += tS[nt][2];
            tS[nt][3] = ex2f(fmaf(tS[nt][3], CEXP, nmc1)); s1 += tS[nt][3];
        }
        s0 += __shfl_xor_sync(0xffffffffu, s0, 1);
        s0 += __shfl_xor_sync(0xffffffffu, s0, 2);
        s1 += __shfl_xor_sync(0xffffffffu, s1, 1);
        s1 += __shfl_xor_sync(0xffffffffu, s1, 2);
        lrun0 = lrun0 * a0 + s0;
        lrun1 = lrun1 * a1 + s1;
        #pragma unroll
        for (int g = 0; g < 8; g++) {
            ctx[g][0] *= a0; ctx[g][1] *= a0;
            ctx[g][2] *= a1; ctx[g][3] *= a1;
        }

        // ---- ctx += P V, term-major with 2-g batching ----
        #pragma unroll
        for (int c = 0; c < 4; c++) {
            uint32_t ph4[4], pl4[4];
            packhl(tS[2*c][0],   tS[2*c][1],   ph4[0], pl4[0]);
            packhl(tS[2*c][2],   tS[2*c][3],   ph4[1], pl4[1]);
            packhl(tS[2*c+1][0], tS[2*c+1][1], ph4[2], pl4[2]);
            packhl(tS[2*c+1][2], tS[2*c+1][3], ph4[3], pl4[3]);
            const uint32_t vrow  = (uint32_t)(c * 16 + (lane & 7) + ((lane >> 3) & 1) * 8);
            const uint32_t vcolb = (((uint32_t)lane >> 4) << 4);
            #pragma unroll
            for (int gp = 0; gp < 2; gp++) {
                uint32_t vh4[2][4], vl4[2][4];
                #pragma unroll
                for (int gg = 0; gg < 2; gg++) {
                    const uint32_t sw = swz(vrow * 128u + vcolb + (uint32_t)(gp * 2 + gg) * 32u);
                    ldsm4t(vh4[gg], VhB + sw);
                    ldsm4t(vl4[gg], VlB + sw);
                }
                #pragma unroll
                for (int gg = 0; gg < 2; gg++)
                    #pragma unroll
                    for (int q = 0; q < 2; q++)
                        mma_bf16(ctx[(gp * 2 + gg) * 2 + q], ph4, vh4[gg] + q * 2);
                #pragma unroll
                for (int gg = 0; gg < 2; gg++)
                    #pragma unroll
                    for (int q = 0; q < 2; q++)
                        mma_bf16(ctx[(gp * 2 + gg) * 2 + q], ph4, vl4[gg] + q * 2);
                #pragma unroll
                for (int gg = 0; gg < 2; gg++)
                    #pragma unroll
                    for (int q = 0; q < 2; q++)
                        mma_bf16(ctx[(gp * 2 + gg) * 2 + q], pl4, vh4[gg] + q * 2);
            }
        }
        __syncthreads();
    }

    // ---- epilogue ----
    const float inv0 = 1.f / lrun0, inv1 = 1.f / lrun1;
    const int b_ = bh >> 4, h_ = bh & 15;
    const int q0 = bm + wm + (lane >> 2);
    #pragma unroll
    for (int g = 0; g < 8; g++) {
        const int col = h_ * 64 + g * 8 + (lane & 3) * 2;
        #pragma unroll
        for (int rr = 0; rr < 2; rr++) {
            const int q = q0 + rr * 8;
            const float inv = rr ? inv1 : inv0;
            const float x0 = ctx[g][rr * 2 + 0] * inv, x1 = ctx[g][rr * 2 + 1] * inv;
            uint32_t ph, pl; packhl(x0, x1, ph, pl);
            const size_t o = ((size_t)b_ * SEQ + q) * DM + col;
            *reinterpret_cast<uint32_t*>(Ch + o) = ph;
            *reinterpret_cast<uint32_t*>(Cl + o) = pl;
        }
    }
}

// ---------------- launch ----------------
extern "C" void kernel_launch(void* const* d_in, const int* in_sizes, int n_in,
                              void* d_out, int out_size)
{
    const float* iQ   = (const float*)d_in[0];
    const float* iK   = (const float*)d_in[1];
    const float* iV   = (const float*)d_in[2];
    const float* Wq   = (const float*)d_in[3];
    const float* Wk   = (const float*)d_in[4];
    const float* Wv   = (const float*)d_in[5];
    const float* Wo   = (const float*)d_in[6];
    const float* pemb = (const float*)d_in[7];
    float* out = (float*)d_out;

    bf16 *Wth, *Wtl, *Xh, *Xl, *QKVh, *QKVl, *Ch, *Cl;
    cudaGetSymbolAddress((void**)&Wth,  g_Wth);
    cudaGetSymbolAddress((void**)&Wtl,  g_Wtl);
    cudaGetSymbolAddress((void**)&Xh,   g_Xh);
    cudaGetSymbolAddress((void**)&Xl,   g_Xl);
    cudaGetSymbolAddress((void**)&QKVh, g_QKVh);
    cudaGetSymbolAddress((void**)&QKVl, g_QKVl);
    cudaGetSymbolAddress((void**)&Ch,   g_Ch);
    cudaGetSymbolAddress((void**)&Cl,   g_Cl);

    constexpr size_t SEC = (size_t)BH * SEQ * AD;
    constexpr long   SXA = (long)NB * SEQ * DM;

    constexpr int SM_GEMM  = 2 * 32768;                                 // 65536
    constexpr int SM_FLASH = 1024 + 16384 + 2 * 32768
                           + 64 * NPE * 4 + NPE * AD * 4;               // 99840
    cudaFuncSetAttribute(gemm_hl<0>, cudaFuncAttributeMaxDynamicSharedMemorySize, SM_GEMM);
    cudaFuncSetAttribute(gemm_hl<1>, cudaFuncAttributeMaxDynamicSharedMemorySize, SM_GEMM);
    cudaFuncSetAttribute(flash_attn, cudaFuncAttributeMaxDynamicSharedMemorySize, SM_FLASH);

    // 0) prep
    transp_w<<<dim3(DM / 32, DM / 32, 4), 256>>>(Wq, Wk, Wv, Wo, Wth, Wtl);
    split_in3<<<dim3(NB * SEQ * DM / 4 / 256, 3), 256>>>(
        (const float4*)iQ, (const float4*)iK, (const float4*)iV, Xh, Xl);

    // 1) projections (batched z = {Q,K,V})
    gemm_hl<1><<<dim3(8, 32, 3), 256, SM_GEMM>>>(
        Xh, Xl, Wth, Wtl, nullptr, QKVh, QKVl, DM, SXA, (long)DM * DM, (long)SEC);

    // 2) fused attention
    flash_attn<<<dim3(SEQ / 64, BH), 128, SM_FLASH>>>(
        QKVh, QKVl, QKVh + SEC, QKVl + SEC, QKVh + 2 * SEC, QKVl + 2 * SEC, pemb, Ch, Cl);

    // 3) out = ctx @ Wo
    gemm_hl<0><<<dim3(8, 32, 1), 256, SM_GEMM>>>(
        Ch, Cl, Wth + (size_t)3 * DM * DM, Wtl + (size_t)3 * DM * DM,
        out, nullptr, nullptr, DM, 0, 0, 0);
}